// round 14
// baseline (speedup 1.0000x reference)
#include <cuda_runtime.h>
#include <cstdint>

// Problem constants
#define NB     16
#define NFREQ  513
#define NT     4000
#define NFFT   1024
#define HOP    256
#define OUT_PER_B (3999 * 256)   // 1023744

#define THREADS 256
#define G_HOPS  13               // output hops per block
#define NFRAMES 16               // frames per block (13 + 3 halo)
#define CHUNK   (G_HOPS * HOP)   // 3328
#define NCHUNK  ((OUT_PER_B + CHUNK - 1) / CHUNK)   // 308

#define FROW    1056             // frame row stride (floats)
#define ZBLK    36               // words per 16-complex block (conflict-free LDS.128)
#define ZFRAME  1156             // words per staged frame (even)

// parity-preserving skew: +2 floats per 64-float block (keeps float2 alignment)
#define SKEW(n) ((n) + (((n) >> 6) << 1))

// SMEM layout (floats)
#define SM_FBUF 0
#define SM_ZST  (SM_FBUF + NFRAMES * FROW)          // 16896
#define SM_TW   (SM_ZST + 8 * ZFRAME)               // 26144
#define SM_WIN  (SM_TW + 1024)                      // 27168
#define SM_IENV (SM_WIN + 1056)                     // 28224
#define SM_FLOATS (SM_IENV + 256)                   // 28480
#define SMEM_BYTES (SM_FLOATS * 4)                  // 113920 B -> 2 blocks/SM

// Twiddle table e^{+2*pi*i*j/1024}, j = 0..511
__device__ float2 g_tw[512];

// e^{+2*pi*i*j/32}
__constant__ float W32C[32] = {
     1.000000000f,  0.980785280f,  0.923879533f,  0.831469612f,
     0.707106781f,  0.555570233f,  0.382683432f,  0.195090322f,
     0.000000000f, -0.195090322f, -0.382683432f, -0.555570233f,
    -0.707106781f, -0.831469612f, -0.923879533f, -0.980785280f,
    -1.000000000f, -0.980785280f, -0.923879533f, -0.831469612f,
    -0.707106781f, -0.555570233f, -0.382683432f, -0.195090322f,
     0.000000000f,  0.195090322f,  0.382683432f,  0.555570233f,
     0.707106781f,  0.831469612f,  0.923879533f,  0.980785280f
};
__constant__ float W32S[32] = {
     0.000000000f,  0.195090322f,  0.382683432f,  0.555570233f,
     0.707106781f,  0.831469612f,  0.923879533f,  0.980785280f,
     1.000000000f,  0.980785280f,  0.923879533f,  0.831469612f,
     0.707106781f,  0.555570233f,  0.382683432f,  0.195090322f,
     0.000000000f, -0.195090322f, -0.382683432f, -0.555570233f,
    -0.707106781f, -0.831469612f, -0.923879533f, -0.980785280f,
    -1.000000000f, -0.980785280f, -0.923879533f, -0.831469612f,
    -0.707106781f, -0.555570233f, -0.382683432f, -0.195090322f
};

__global__ void tw_init_kernel() {
    int j = blockIdx.x * 256 + threadIdx.x;
    if (j < 512) {
        float s, c;
        sincospif((float)j * (1.0f / 512.0f), &s, &c);   // 2*pi*j/1024
        g_tw[j] = make_float2(c, s);
    }
}

__device__ __forceinline__ float2 cmul(float2 a, float2 b) {
    return make_float2(a.x * b.x - a.y * b.y, a.x * b.y + a.y * b.x);
}

// ---------------------------------------------------------------------------
// 16-point inverse DFT in registers (radix-4 x radix-4), natural in/out.
// ---------------------------------------------------------------------------
__device__ __forceinline__ void ifft16(float2 v[16]) {
    float2 g[16];
#pragma unroll
    for (int j1 = 0; j1 < 4; j1++) {
        float2 a = v[j1], b = v[j1 + 4], c = v[j1 + 8], d = v[j1 + 12];
        float t0x = a.x + c.x, t0y = a.y + c.y;
        float t1x = a.x - c.x, t1y = a.y - c.y;
        float t2x = b.x + d.x, t2y = b.y + d.y;
        float t3x = b.x - d.x, t3y = b.y - d.y;
        g[j1 * 4 + 0] = make_float2(t0x + t2x, t0y + t2y);
        g[j1 * 4 + 1] = make_float2(t1x - t3y, t1y + t3x);
        g[j1 * 4 + 2] = make_float2(t0x - t2x, t0y - t2y);
        g[j1 * 4 + 3] = make_float2(t1x + t3y, t1y - t3x);
    }
#pragma unroll
    for (int j1 = 1; j1 < 4; j1++) {
#pragma unroll
        for (int m2 = 1; m2 < 4; m2++) {
            float wc = W32C[2 * j1 * m2];
            float ws = W32S[2 * j1 * m2];
            float2 x = g[j1 * 4 + m2];
            g[j1 * 4 + m2] = make_float2(x.x * wc - x.y * ws, x.x * ws + x.y * wc);
        }
    }
#pragma unroll
    for (int m2 = 0; m2 < 4; m2++) {
        float2 a = g[m2], b = g[4 + m2], c = g[8 + m2], d = g[12 + m2];
        float t0x = a.x + c.x, t0y = a.y + c.y;
        float t1x = a.x - c.x, t1y = a.y - c.y;
        float t2x = b.x + d.x, t2y = b.y + d.y;
        float t3x = b.x - d.x, t3y = b.y - d.y;
        v[m2 + 0]  = make_float2(t0x + t2x, t0y + t2y);
        v[m2 + 4]  = make_float2(t1x - t3y, t1y + t3x);
        v[m2 + 8]  = make_float2(t0x - t2x, t0y - t2y);
        v[m2 + 12] = make_float2(t1x + t3y, t1y - t3x);
    }
}

// ---------------------------------------------------------------------------
// Fused kernel. grid = (NCHUNK, NB), block = 256 (8 warps), 2 blocks/SM.
// ---------------------------------------------------------------------------
__global__ void __launch_bounds__(THREADS, 2)
istft_fused_kernel(const float* __restrict__ mag,
                   const float* __restrict__ cosp,
                   const float* __restrict__ sinp,
                   const float* __restrict__ window,
                   float* __restrict__ out) {
    extern __shared__ float smem[];
    float*  fbuf  = smem + SM_FBUF;
    float*  zst   = smem + SM_ZST;
    float2* tw    = reinterpret_cast<float2*>(smem + SM_TW);
    float*  win_s = smem + SM_WIN;
    float*  ienv  = smem + SM_IENV;

    const int tid  = threadIdx.x;
    const int w    = tid >> 5;
    const int lane = tid & 31;
    const int c    = blockIdx.x;
    const int b    = blockIdx.y;
    const int ft0  = G_HOPS * c - 1;

    // ---- tables ----
    for (int j = tid; j < 512; j += THREADS) tw[j] = g_tw[j];
    for (int j = tid; j < 1024; j += THREADS)
        win_s[SKEW(j)] = window[j] * (1.0f / 1024.0f);
    {   // interior inverse envelope: env(s) depends only on s mod 256
        float e = 0.0f;
#pragma unroll
        for (int q = 0; q < 4; q++) {
            float wv = window[tid + 256 * q];
            e += wv * wv;
        }
        ienv[tid] = 1.0f / (e + 1e-11f);
    }
    __syncthreads();

    const size_t bbase = (size_t)b * NFREQ * NT;
    const int n1 = __brev(lane) >> 27;               // bitrev5(lane)

    // ---- two rounds: stage 8 Z-spectra, FFT 8 frames ----
#pragma unroll 1
    for (int r = 0; r < 2; r++) {
        // stage: thread handles conjugate pair (k, 512-k) for one frame
        {
            const int t_off = tid & 7;
            const int f_off = tid >> 3;              // 0..31
            const int t = ft0 + r * 8 + t_off;
            if (t >= 0 && t < NT) {
                float* zb = zst + t_off * ZFRAME;
                const float* pm = mag  + bbase + (size_t)t;
                const float* pc = cosp + bbase + (size_t)t;
                const float* ps = sinp + bbase + (size_t)t;
                int ka = f_off * NT;                 // k index offset
                int kb = (512 - f_off) * NT;         // mirror index offset
#pragma unroll 4
                for (int i = 0; i < 8; i++) {
                    const int k  = f_off + 32 * i;   // 0..255
                    const int km = 512 - k;          // 257..512
                    float ma = pm[ka], ca = pc[ka], sa = ps[ka];
                    float mb = pm[kb], cb = pc[kb], sb = ps[kb];
                    float ax = ma * ca, ay = ma * sa;
                    float bx = mb * cb, by = mb * sb;
                    if (k == 0) { ay = 0.0f; by = 0.0f; }
                    float2 W = tw[k];
                    float qx = ax - bx, qy = ay + by;
                    float S = ax + bx, D = ay - by;
                    float T = W.x * qy + W.y * qx;
                    float U = W.x * qx - W.y * qy;
                    // Z[k]
                    {
                        int a0 = ZBLK * (k >> 4) + 2 * (k & 15);
                        *reinterpret_cast<float2*>(zb + a0) = make_float2(S - T, D + U);
                    }
                    // Z[512-k]
                    if (k > 0) {
                        int a1 = ZBLK * (km >> 4) + 2 * (km & 15);
                        *reinterpret_cast<float2*>(zb + a1) = make_float2(S + T, U - D);
                    }
                    ka += 32 * NT;
                    kb -= 32 * NT;
                }
                // epilogue: k = 256 (self-conjugate)
                if (f_off == 0) {
                    const int kc = 256 * NT;
                    float ma = pm[kc], ca = pc[kc], sa = ps[kc];
                    float ax = ma * ca, ay = ma * sa;
                    *reinterpret_cast<float2*>(zb + ZBLK * 16) =
                        make_float2(2.0f * ax, -2.0f * ay);
                }
            }
        }
        __syncthreads();

        // FFT: warp w handles staged frame w
        const int slot = r * 8 + w;
        const int t = ft0 + slot;
        if (t >= 0 && t < NT) {
            // load 16 contiguous complex per lane: k = 16*lane + k2
            float2 v[16];
            {
                const float4* zr = reinterpret_cast<const float4*>(zst + w * ZFRAME + ZBLK * lane);
#pragma unroll
                for (int j = 0; j < 8; j++) {
                    float4 q = zr[j];
                    v[2 * j]     = make_float2(q.x, q.y);
                    v[2 * j + 1] = make_float2(q.z, q.w);
                }
            }

            // cross-lane 32-pt inverse DIF over k1 = lane; output lane holds n1
#pragma unroll
            for (int s = 0; s < 5; s++) {
                const int h = 16 >> s;
                const float wc = W32C[(lane & (h - 1)) << s];
                const float ws = W32S[(lane & (h - 1)) << s];
                const bool hi = (lane & h) != 0;
#pragma unroll
                for (int k2 = 0; k2 < 16; k2++) {
                    float px = __shfl_xor_sync(0xffffffffu, v[k2].x, h);
                    float py = __shfl_xor_sync(0xffffffffu, v[k2].y, h);
                    float2 rr;
                    if (hi) {
                        float dx = px - v[k2].x;
                        float dy = py - v[k2].y;
                        rr = make_float2(dx * wc - dy * ws, dx * ws + dy * wc);
                    } else {
                        rr = make_float2(v[k2].x + px, v[k2].y + py);
                    }
                    v[k2] = rr;
                }
            }

            // mid twiddle: v[k2] *= W512^{k2*n1} via power recurrence
            {
                float2 Wb = tw[2 * n1];
                float2 Wc = Wb;
#pragma unroll
                for (int k2 = 1; k2 < 16; k2++) {
                    v[k2] = cmul(v[k2], Wc);
                    Wc = cmul(Wc, Wb);
                }
            }

            // 16-pt register IDFT over k2 -> n2 (natural order)
            ifft16(v);

            // windowed store: lane n1 owns samples n = 2*n1 + 64*n2 (+1)
            float* frow = fbuf + slot * FROW;
#pragma unroll
            for (int n2 = 0; n2 < 16; n2++) {
                const int n  = 2 * n1 + (n2 << 6);
                const int ni = SKEW(n);              // = n + 2*n2, even
                float2 wv = *reinterpret_cast<const float2*>(win_s + ni);
                *reinterpret_cast<float2*>(frow + ni) =
                    make_float2(v[n2].x * wv.x, v[n2].y * wv.y);
            }
        }
        __syncthreads();
    }

    // ---- overlap-add + normalize + trim ----
    const int j0 = c * CHUNK;
    float* outb = out + (size_t)b * OUT_PER_B;

    if (c > 0 && c < NCHUNK - 1) {
        // interior: exactly 4 frames per sample, env from table; 2 samples/thread
#pragma unroll 1
        for (int i = 0; i < 7; i++) {
            const int p = i * 256 + tid;
            if (p >= CHUNK / 2) break;
            const int j = j0 + 2 * p;
            const int s = j + NFFT / 2;
            const int t0 = (s - 768) >> 8;
            const int r0 = t0 - ft0;
            const int nb = s - (t0 << 8);            // [768,1022], even
            float2 acc = make_float2(0.0f, 0.0f);
#pragma unroll
            for (int q = 0; q < 4; q++) {
                const int n  = nb - (q << 8);
                const int ni = SKEW(n);              // even
                float2 f = *reinterpret_cast<const float2*>(fbuf + (r0 + q) * FROW + ni);
                acc.x += f.x; acc.y += f.y;
            }
            const int m = s & 255;                   // even
            float2 o = make_float2(acc.x * ienv[m], acc.y * ienv[m + 1]);
            *reinterpret_cast<float2*>(outb + j) = o;
        }
    } else {
        // edge blocks: honest env accumulation (win_s is w/1024 -> scale env)
#pragma unroll 1
        for (int i = 0; i < G_HOPS; i++) {
            const int j = j0 + i * HOP + tid;
            if (j >= OUT_PER_B) break;
            const int s = j + NFFT / 2;
            int thi = s >> 8; if (thi > NT - 1) thi = NT - 1;
            int tlo = (s - 768) >> 8; if (tlo < 0) tlo = 0;
            float acc = 0.0f, env = 0.0f;
#pragma unroll 4
            for (int t = tlo; t <= thi; t++) {
                const int n  = s - (t << 8);
                const int ni = SKEW(n);
                acc += fbuf[(t - ft0) * FROW + ni];
                float wv = win_s[ni];
                env += wv * wv;
            }
            outb[j] = acc / (env * 1048576.0f + 1e-11f);
        }
    }
}

// ---------------------------------------------------------------------------
extern "C" void kernel_launch(void* const* d_in, const int* in_sizes, int n_in,
                              void* d_out, int out_size) {
    const float* mag    = (const float*)d_in[0];
    const float* cosp   = (const float*)d_in[1];
    const float* sinp   = (const float*)d_in[2];
    const float* window = (const float*)d_in[3];
    float* out = (float*)d_out;

    cudaFuncSetAttribute(istft_fused_kernel,
                         cudaFuncAttributeMaxDynamicSharedMemorySize, SMEM_BYTES);

    tw_init_kernel<<<2, 256>>>();

    dim3 grid(NCHUNK, NB);   // 308 x 16
    istft_fused_kernel<<<grid, THREADS, SMEM_BYTES>>>(mag, cosp, sinp, window, out);
}